// round 4
// baseline (speedup 1.0000x reference)
#include <cuda_runtime.h>
#include <cuda_bf16.h>

#define Tn 100
#define Bn 16
#define En 128
#define Hn 256
#define Ln 2048
#define H2n 512
#define G4n 1024
#define NCH 32          // ctx l-chunks
#define CHL 64          // l per ctx chunk

#define OFF_OUT  0
#define OFF_HF   (Tn*Bn*Hn)
#define OFF_CF   (OFF_HF + Bn*Hn)
#define OFF_ATTN (OFF_CF + Bn*Hn)
#define OFF_PG   (OFF_ATTN + Tn*Bn*Ln)

// ------------- scratch -------------
__device__ float g_x[Tn*Bn*En];
__device__ float g_xw[Tn*Bn*G4n];
__device__ float g_ef[Bn*Ln*Hn];
__device__ float g_e[Bn*Ln];
__device__ float g_m[Bn*16];
__device__ float g_s[Bn*16];
__device__ float g_h[2][Bn*Hn];
__device__ float g_c[2][Bn*Hn];
__device__ float g_dec[Bn*Hn];
__device__ float g_ctxp[Bn*NCH*H2n];
// transposed weights (k-major so per-thread dots are coalesced)
__device__ float g_WhhT[Hn*G4n];     // [k][g]
__device__ float g_WsT[H2n*Hn];      // [k][h]
__device__ float g_WoutT[768*Hn];    // [k][h]

// ------------- helpers -------------
__device__ __forceinline__ float warp_sum(float v) {
    #pragma unroll
    for (int o = 16; o > 0; o >>= 1) v += __shfl_xor_sync(0xffffffffu, v, o);
    return v;
}
__device__ __forceinline__ float warp_max(float v) {
    #pragma unroll
    for (int o = 16; o > 0; o >>= 1) v = fmaxf(v, __shfl_xor_sync(0xffffffffu, v, o));
    return v;
}
__device__ __forceinline__ float tanh_acc(float x) {   // accurate: LSTM recurrence
    float ax = fabsf(x);
    float e  = __expf(-2.0f * ax);
    float r  = __fdividef(1.0f - e, 1.0f + e);
    return copysignf(r, x);
}
__device__ __forceinline__ float tanh_fast(float x) {  // MUFU.TANH: attention scores
    float y;
    asm("tanh.approx.f32 %0, %1;" : "=f"(y) : "f"(x));
    return y;
}
__device__ __forceinline__ float sigmoidf_(float x) {
    return __fdividef(1.0f, 1.0f + __expf(-x));
}
__device__ __forceinline__ float4 ld4(const float* p) { return *(const float4*)p; }

// ------------- prep: h/c init + weight transposes -------------
__global__ void k_prep(const float* __restrict__ h0, const float* __restrict__ c0,
                       const float* __restrict__ Whh, const float* __restrict__ Ws,
                       const float* __restrict__ Wout) {
    int nt = gridDim.x * blockDim.x;
    int t0 = blockIdx.x * blockDim.x + threadIdx.x;
    for (int i = t0; i < Bn*Hn; i += nt) { g_h[0][i] = h0[i]; g_c[0][i] = c0[i]; }
    for (int i = t0; i < Hn*G4n; i += nt) {
        int g = i & (G4n-1), k = i >> 10;
        g_WhhT[k*G4n + g] = Whh[g*Hn + k];
    }
    for (int i = t0; i < H2n*Hn; i += nt) {
        int h = i & (Hn-1), k = i >> 8;
        g_WsT[k*Hn + h] = Ws[h*H2n + k];
    }
    for (int i = t0; i < 768*Hn; i += nt) {
        int h = i & (Hn-1), k = i >> 8;
        g_WoutT[k*Hn + h] = Wout[h*768 + k];
    }
}

// ------------- x and x@Wih.T for all (t,b) -------------
__global__ __launch_bounds__(256) void k_xfuse(const float* __restrict__ dec,
        const float* __restrict__ Wx, const float* __restrict__ bx,
        const float* __restrict__ Wih, const float* __restrict__ bih) {
    __shared__ float sin_[8][En];
    __shared__ float sx2[8][En];
    int r0 = blockIdx.x * 8;
    int tid = threadIdx.x;
    for (int idx = tid; idx < 8*En; idx += 256)
        sin_[idx >> 7][idx & 127] = dec[(r0 + (idx >> 7))*En + (idx & 127)];
    __syncthreads();
    {
        int j = tid & 127, rg = tid >> 7;
        float acc[4] = {0.f, 0.f, 0.f, 0.f};
        #pragma unroll 8
        for (int k = 0; k < En; k += 4) {
            float4 w = ld4(&Wx[j*640 + k]);
            #pragma unroll
            for (int rr = 0; rr < 4; rr++) {
                const float* s = sin_[rg*4 + rr];
                acc[rr] += w.x*s[k] + w.y*s[k+1] + w.z*s[k+2] + w.w*s[k+3];
            }
        }
        float bb = bx[j];
        #pragma unroll
        for (int rr = 0; rr < 4; rr++) {
            float val = acc[rr] + bb;
            sx2[rg*4 + rr][j] = val;
            g_x[(r0 + rg*4 + rr)*En + j] = val;
        }
    }
    __syncthreads();
    for (int q = 0; q < 4; q++) {
        int g = q*256 + tid;
        float acc[8];
        #pragma unroll
        for (int r = 0; r < 8; r++) acc[r] = 0.f;
        #pragma unroll 4
        for (int k = 0; k < En; k += 4) {
            float4 w = ld4(&Wih[g*En + k]);
            #pragma unroll
            for (int r = 0; r < 8; r++)
                acc[r] += w.x*sx2[r][k] + w.y*sx2[r][k+1] + w.z*sx2[r][k+2] + w.w*sx2[r][k+3];
        }
        float bb = bih[g];
        #pragma unroll
        for (int r = 0; r < 8; r++) g_xw[(r0 + r)*G4n + g] = acc[r] + bb;
    }
}

// ------------- enc_feat = es @ Wh.T + bh -------------
__global__ __launch_bounds__(256) void k_encfeat(const float* __restrict__ es,
        const float* __restrict__ Wh, const float* __restrict__ bh) {
    __shared__ float sW[32*261];
    __shared__ float sE[32*36];
    int b  = blockIdx.x >> 6;
    int l0 = (blockIdx.x & 63) * 32;
    int tid = threadIdx.x, lane = tid & 31, w = tid >> 5;
    float acc[32];
    #pragma unroll
    for (int i = 0; i < 32; i++) acc[i] = 0.f;
    for (int k0 = 0; k0 < H2n; k0 += 32) {
        #pragma unroll 4
        for (int hh = 0; hh < 32; hh++) {
            int h = w*32 + hh;
            sW[lane*261 + h] = Wh[h*H2n + k0 + lane];
        }
        for (int idx = tid; idx < 1024; idx += 256) {
            int l = idx >> 5, k = idx & 31;
            sE[k*36 + l] = es[(size_t)(b*Ln + l0 + l)*H2n + k0 + k];
        }
        __syncthreads();
        #pragma unroll 4
        for (int k = 0; k < 32; k++) {
            float wv = sW[k*261 + tid];
            #pragma unroll
            for (int i4 = 0; i4 < 8; i4++) {
                float4 e = ld4(&sE[k*36 + i4*4]);
                acc[i4*4+0] += e.x*wv; acc[i4*4+1] += e.y*wv;
                acc[i4*4+2] += e.z*wv; acc[i4*4+3] += e.w*wv;
            }
        }
        __syncthreads();
    }
    float bb = bh[tid];
    #pragma unroll
    for (int i = 0; i < 32; i++)
        g_ef[(size_t)(b*Ln + l0 + i)*Hn + tid] = acc[i] + bb;
}

// ------------- fused per-step: epilogue(t-1) + LSTM(t) + dec_feat(t) -------------
// grid = Bn blocks (one per batch), 512 threads
__global__ __launch_bounds__(512) void k_step(int t,
        const float* __restrict__ bhh,
        const float* __restrict__ bout,
        const float* __restrict__ Wpg, const float* __restrict__ bpg,
        const float* __restrict__ bs,
        float* __restrict__ out) {
    __shared__ float sh[Hn], sc[Hn], sctx[H2n];
    __shared__ float shn[Hn], scn[Hn];
    __shared__ float sgp[2*Hn*4];    // gate partials [kh][j][gate]
    __shared__ float spart[512];
    int b = blockIdx.x;
    int tid = threadIdx.x, lane = tid & 31;
    int pin = t & 1;

    // ---- load state + reduce ctx partials ----
    if (tid < Hn) { sh[tid] = g_h[pin][b*Hn + tid]; sc[tid] = g_c[pin][b*Hn + tid]; }
    if (t > 0) {
        float s = 0.f;
        #pragma unroll 8
        for (int p = 0; p < NCH; p++) s += g_ctxp[(b*NCH + p)*H2n + tid];
        sctx[tid] = s;
    }
    __syncthreads();

    // ---- partial dots: LSTM gates (t<Tn) and outputs[t-1] (t>0) ----
    int j  = tid & 255;
    int kh = tid >> 8;              // 0/1 split of k-range
    float ga[4] = {0.f, 0.f, 0.f, 0.f};
    if (t < Tn) {
        int k0 = kh * 128;
        #pragma unroll 4
        for (int k = k0; k < k0 + 128; k++) {
            float hv = sh[k];
            const float* wr = &g_WhhT[k*G4n + j];
            ga[0] += wr[0]     * hv;
            ga[1] += wr[256]   * hv;
            ga[2] += wr[512]   * hv;
            ga[3] += wr[768]   * hv;
        }
        #pragma unroll
        for (int g4 = 0; g4 < 4; g4++) sgp[(kh*Hn + j)*4 + g4] = ga[g4];
    }
    float oacc = 0.f;
    if (t > 0) {
        int k0 = kh * 384;
        #pragma unroll 4
        for (int k = k0; k < k0 + 384; k++) {
            float val = (k < Hn) ? sh[k] : sctx[k - Hn];
            oacc += g_WoutT[k*Hn + j] * val;
        }
        spart[tid] = oacc;
    }
    __syncthreads();

    // ---- combine: h/c update, outputs, p_gen ----
    if (t < Tn && tid < Hn) {
        float gi_ = sgp[tid*4+0] + sgp[(Hn+tid)*4+0];
        float gf  = sgp[tid*4+1] + sgp[(Hn+tid)*4+1];
        float gg  = sgp[tid*4+2] + sgp[(Hn+tid)*4+2];
        float go  = sgp[tid*4+3] + sgp[(Hn+tid)*4+3];
        const float* xw = &g_xw[(t*Bn + b)*G4n];
        gi_ += xw[tid]        + bhh[tid];
        gf  += xw[Hn + tid]   + bhh[Hn + tid];
        gg  += xw[2*Hn + tid] + bhh[2*Hn + tid];
        go  += xw[3*Hn + tid] + bhh[3*Hn + tid];
        float cn = sigmoidf_(gf)*sc[tid] + sigmoidf_(gi_)*tanh_acc(gg);
        float hn = sigmoidf_(go)*tanh_acc(cn);
        g_c[pin ^ 1][b*Hn + tid] = cn;
        g_h[pin ^ 1][b*Hn + tid] = hn;
        shn[tid] = hn; scn[tid] = cn;
    }
    if (t > 0) {
        if (tid >= 256 && tid < 512-32) {
            // nothing
        }
        if (tid < Hn && 0) {}
        if (tid >= Hn && tid < Hn + 32) {
            // p_gen by warp 8: dot over [ctx, h, c, x] (1152)
            float acc = 0.f;
            for (int idx = lane; idx < 1152; idx += 32) {
                float val = (idx < 512)  ? sctx[idx]
                          : (idx < 768)  ? sh[idx - 512]
                          : (idx < 1024) ? sc[idx - 768]
                                         : g_x[((t-1)*Bn + b)*En + idx - 1024];
                acc += val * Wpg[idx];
            }
            acc = warp_sum(acc);
            if (lane == 0) out[OFF_PG + (t-1)*Bn + b] = sigmoidf_(acc + bpg[0]);
        }
    }
    __syncthreads();
    if (t > 0 && tid < Hn)
        out[OFF_OUT + ((t-1)*Bn + b)*Hn + tid] = spart[tid] + spart[Hn + tid] + bout[tid];

    if (t == Tn) {
        if (tid < Hn) {
            out[OFF_HF + b*Hn + tid] = sh[tid];
            out[OFF_CF + b*Hn + tid] = sc[tid];
        }
        return;
    }

    // ---- dec_feat = [h_new; c_new] @ Ws.T + bs ----
    float dacc = 0.f;
    {
        int k0 = kh * 256;
        #pragma unroll 4
        for (int k = k0; k < k0 + 256; k++) {
            float val = (k < Hn) ? shn[k] : scn[k - Hn];
            dacc += g_WsT[k*Hn + j] * val;
        }
    }
    __syncthreads();          // spart reads above done
    spart[tid] = dacc;
    __syncthreads();
    if (tid < Hn) g_dec[b*Hn + tid] = spart[tid] + spart[Hn + tid] + bs[tid];
}

// ------------- scores + per-chunk softmax partials (16 chunks of 128) -------------
__global__ __launch_bounds__(256) void k_scores(int t,
        const float* __restrict__ v, const float* __restrict__ mask) {
    __shared__ float sD[Hn], sV[Hn], sE[128], red[8];
    int b = blockIdx.x >> 4, lc = blockIdx.x & 15;
    int l0 = lc * 128;
    int tid = threadIdx.x, lane = tid & 31, w = tid >> 5;
    sD[tid] = g_dec[b*Hn + tid];
    sV[tid] = v[tid];
    __syncthreads();
    for (int i = 0; i < 16; i++) {
        int l = l0 + w*16 + i;
        const float* ef = &g_ef[(size_t)(b*Ln + l)*Hn];
        float acc = 0.f;
        #pragma unroll
        for (int q = 0; q < 2; q++) {
            int k = q*128 + lane*4;
            float4 e4 = ld4(&ef[k]);
            acc += sV[k  ] * tanh_fast(e4.x + sD[k  ]);
            acc += sV[k+1] * tanh_fast(e4.y + sD[k+1]);
            acc += sV[k+2] * tanh_fast(e4.z + sD[k+2]);
            acc += sV[k+3] * tanh_fast(e4.w + sD[k+3]);
        }
        acc = warp_sum(acc);
        if (lane == 0) { g_e[b*Ln + l] = acc; sE[w*16 + i] = acc; }
    }
    __syncthreads();
    float x = (tid < 128) ? sE[tid] : -1e30f;
    float mx = warp_max(x);
    if (lane == 0) red[w] = mx;
    __syncthreads();
    float m = red[0];
    #pragma unroll
    for (int i = 1; i < 8; i++) m = fmaxf(m, red[i]);
    float ex = (tid < 128) ? __expf(sE[tid] - m) * mask[b*Ln + l0 + tid] : 0.f;
    __syncthreads();
    float sx = warp_sum(ex);
    if (lane == 0) red[w] = sx;
    __syncthreads();
    if (tid == 0) {
        float s = 0.f;
        #pragma unroll
        for (int i = 0; i < 8; i++) s += red[i];
        g_m[b*16 + lc] = m;
        g_s[b*16 + lc] = s;
    }
}

// ------------- attn + ctx partials (32 chunks of 64) -------------
__global__ __launch_bounds__(256) void k_ctx(int t,
        const float* __restrict__ es, const float* __restrict__ mask,
        float* __restrict__ out) {
    __shared__ float sA[CHL];
    int b = blockIdx.x >> 5, ch = blockIdx.x & 31;
    int l0 = ch * CHL;
    int tid = threadIdx.x;
    float M = -1e30f;
    #pragma unroll
    for (int c = 0; c < 16; c++) M = fmaxf(M, g_m[b*16 + c]);
    float S = 0.f;
    #pragma unroll
    for (int c = 0; c < 16; c++) S += g_s[b*16 + c] * __expf(g_m[b*16 + c] - M);
    float invS = __fdividef(1.f, S);
    if (tid < CHL) {
        int l = l0 + tid;
        float a = __expf(g_e[b*Ln + l] - M) * mask[b*Ln + l] * invS;
        out[OFF_ATTN + (size_t)(t*Bn + b)*Ln + l] = a;
        sA[tid] = a;
    }
    __syncthreads();
    float acc0 = 0.f, acc1 = 0.f;
    #pragma unroll 4
    for (int l = 0; l < CHL; l++) {
        float a = sA[l];
        const float* row = &es[(size_t)(b*Ln + l0 + l)*H2n];
        acc0 += a * row[tid];
        acc1 += a * row[tid + 256];
    }
    g_ctxp[(b*NCH + ch)*H2n + tid]       = acc0;
    g_ctxp[(b*NCH + ch)*H2n + tid + 256] = acc1;
}

// ------------- launcher -------------
extern "C" void kernel_launch(void* const* d_in, const int* in_sizes, int n_in,
                              void* d_out, int out_size) {
    const float* dec  = (const float*)d_in[0];
    const float* h0   = (const float*)d_in[1];
    const float* c0   = (const float*)d_in[2];
    const float* es   = (const float*)d_in[3];
    const float* mask = (const float*)d_in[4];
    const float* Wh   = (const float*)d_in[5];
    const float* bh   = (const float*)d_in[6];
    const float* Ws   = (const float*)d_in[7];
    const float* bs   = (const float*)d_in[8];
    const float* v    = (const float*)d_in[9];
    const float* Wx   = (const float*)d_in[10];
    const float* bx   = (const float*)d_in[11];
    const float* Wih  = (const float*)d_in[12];
    const float* bih  = (const float*)d_in[13];
    const float* Whh  = (const float*)d_in[14];
    const float* bhh  = (const float*)d_in[15];
    const float* Wpg  = (const float*)d_in[16];
    const float* bpg  = (const float*)d_in[17];
    const float* Wout = (const float*)d_in[18];
    const float* bout = (const float*)d_in[19];
    float* out = (float*)d_out;

    k_prep<<<264, 256>>>(h0, c0, Whh, Ws, Wout);
    k_xfuse<<<200, 256>>>(dec, Wx, bx, Wih, bih);
    k_encfeat<<<1024, 256>>>(es, Wh, bh);
    for (int t = 0; t < Tn; t++) {
        k_step<<<Bn, 512>>>(t, bhh, bout, Wpg, bpg, bs, out);
        k_scores<<<256, 256>>>(t, v, mask);
        k_ctx<<<512, 256>>>(t, es, mask, out);
    }
    k_step<<<Bn, 512>>>(Tn, bhh, bout, Wpg, bpg, bs, out);
}

// round 5
// speedup vs baseline: 1.4614x; 1.4614x over previous
#include <cuda_runtime.h>
#include <cuda_bf16.h>

#define Tn 100
#define Bn 16
#define En 128
#define Hn 256
#define Ln 2048
#define H2n 512
#define G4n 1024
#define NSC 64      // score chunks (32 l each)
#define NCC 32      // ctx chunks (64 l each)

#define OFF_OUT  0
#define OFF_HF   (Tn*Bn*Hn)
#define OFF_CF   (OFF_HF + Bn*Hn)
#define OFF_ATTN (OFF_CF + Bn*Hn)
#define OFF_PG   (OFF_ATTN + Tn*Bn*Ln)

// ---------------- scratch ----------------
__device__ float g_x[Tn*Bn*En];
__device__ float g_xw[Tn*Bn*G4n];
__device__ float g_ef[Bn*Ln*Hn];
__device__ float g_e[Bn*Ln];
__device__ float g_m[Bn*NSC];
__device__ float g_s[Bn*NSC];
__device__ float g_hT[2][Hn*Bn];      // [k][b] transposed state
__device__ float g_cT[2][Hn*Bn];
__device__ float g_ctxT[H2n*Bn];      // [e][b]
__device__ float g_dec[Bn*Hn];        // [b][k]
__device__ float g_ctxp[Bn*NCC*H2n];  // [b][chunk][e]
__device__ int   g_cnt[Bn];           // zero-initialized, reset after use

// ---------------- helpers ----------------
__device__ __forceinline__ float warp_sum(float v) {
    #pragma unroll
    for (int o = 16; o > 0; o >>= 1) v += __shfl_xor_sync(0xffffffffu, v, o);
    return v;
}
__device__ __forceinline__ float warp_max(float v) {
    #pragma unroll
    for (int o = 16; o > 0; o >>= 1) v = fmaxf(v, __shfl_xor_sync(0xffffffffu, v, o));
    return v;
}
__device__ __forceinline__ float tanh_acc(float x) {   // accurate (LSTM recurrence)
    float ax = fabsf(x);
    float e  = __expf(-2.0f * ax);
    float r  = __fdividef(1.0f - e, 1.0f + e);
    return copysignf(r, x);
}
__device__ __forceinline__ float tanh_fast(float x) {  // MUFU.TANH (attention scores)
    float y;
    asm("tanh.approx.f32 %0, %1;" : "=f"(y) : "f"(x));
    return y;
}
__device__ __forceinline__ float sigmoidf_(float x) {
    return __fdividef(1.0f, 1.0f + __expf(-x));
}
__device__ __forceinline__ float4 ld4(const float* p) { return *(const float4*)p; }

// ---------------- prep: transpose h0/c0 into [k][b] ----------------
__global__ void k_prep(const float* __restrict__ h0, const float* __restrict__ c0) {
    int i = blockIdx.x * blockDim.x + threadIdx.x;
    if (i < Hn*Bn) {
        int b = i & 15, k = i >> 4;
        g_hT[0][i] = h0[b*Hn + k];
        g_cT[0][i] = c0[b*Hn + k];
    }
}

// ---------------- x and x@Wih.T for all (t,b) ----------------
__global__ __launch_bounds__(256) void k_xfuse(const float* __restrict__ dec,
        const float* __restrict__ Wx, const float* __restrict__ bx,
        const float* __restrict__ Wih, const float* __restrict__ bih) {
    __shared__ float sin_[8][En];
    __shared__ float sx2[8][En];
    int r0 = blockIdx.x * 8;
    int tid = threadIdx.x;
    for (int idx = tid; idx < 8*En; idx += 256)
        sin_[idx >> 7][idx & 127] = dec[(r0 + (idx >> 7))*En + (idx & 127)];
    __syncthreads();
    {
        int j = tid & 127, rg = tid >> 7;
        float acc[4] = {0.f, 0.f, 0.f, 0.f};
        #pragma unroll 8
        for (int k = 0; k < En; k += 4) {
            float4 w = ld4(&Wx[j*640 + k]);
            #pragma unroll
            for (int rr = 0; rr < 4; rr++) {
                const float* s = sin_[rg*4 + rr];
                acc[rr] += w.x*s[k] + w.y*s[k+1] + w.z*s[k+2] + w.w*s[k+3];
            }
        }
        float bb = bx[j];
        #pragma unroll
        for (int rr = 0; rr < 4; rr++) {
            float val = acc[rr] + bb;
            sx2[rg*4 + rr][j] = val;
            g_x[(r0 + rg*4 + rr)*En + j] = val;
        }
    }
    __syncthreads();
    for (int q = 0; q < 4; q++) {
        int g = q*256 + tid;
        float acc[8];
        #pragma unroll
        for (int r = 0; r < 8; r++) acc[r] = 0.f;
        #pragma unroll 4
        for (int k = 0; k < En; k += 4) {
            float4 w = ld4(&Wih[g*En + k]);
            #pragma unroll
            for (int r = 0; r < 8; r++)
                acc[r] += w.x*sx2[r][k] + w.y*sx2[r][k+1] + w.z*sx2[r][k+2] + w.w*sx2[r][k+3];
        }
        float bb = bih[g];
        #pragma unroll
        for (int r = 0; r < 8; r++) g_xw[(r0 + r)*G4n + g] = acc[r] + bb;
    }
}

// ---------------- enc_feat = es @ Wh.T + bh ----------------
__global__ __launch_bounds__(256) void k_encfeat(const float* __restrict__ es,
        const float* __restrict__ Wh, const float* __restrict__ bh) {
    __shared__ float sW[32*261];
    __shared__ float sE[32*36];
    int b  = blockIdx.x >> 6;
    int l0 = (blockIdx.x & 63) * 32;
    int tid = threadIdx.x, lane = tid & 31, w = tid >> 5;
    float acc[32];
    #pragma unroll
    for (int i = 0; i < 32; i++) acc[i] = 0.f;
    for (int k0 = 0; k0 < H2n; k0 += 32) {
        #pragma unroll 4
        for (int hh = 0; hh < 32; hh++) {
            int h = w*32 + hh;
            sW[lane*261 + h] = Wh[h*H2n + k0 + lane];
        }
        for (int idx = tid; idx < 1024; idx += 256) {
            int l = idx >> 5, k = idx & 31;
            sE[k*36 + l] = es[(size_t)(b*Ln + l0 + l)*H2n + k0 + k];
        }
        __syncthreads();
        #pragma unroll 4
        for (int k = 0; k < 32; k++) {
            float wv = sW[k*261 + tid];
            #pragma unroll
            for (int i4 = 0; i4 < 8; i4++) {
                float4 e = ld4(&sE[k*36 + i4*4]);
                acc[i4*4+0] += e.x*wv; acc[i4*4+1] += e.y*wv;
                acc[i4*4+2] += e.z*wv; acc[i4*4+3] += e.w*wv;
            }
        }
        __syncthreads();
    }
    float bb = bh[tid];
    #pragma unroll
    for (int i = 0; i < 32; i++)
        g_ef[(size_t)(b*Ln + l0 + i)*Hn + tid] = acc[i] + bb;
}

// ---------------- k_gates: LSTM gates (t<Tn) + epilogue out/pgen for t-1 ----------------
// grid = 161 blocks x 128 threads.
//   bid 0..127  : gate blocks (2 j x 4 gates each, all 16 b)
//   bid 128..159: out-epilogue blocks (8 h-cols each, all b), t>0
//   bid 160     : pgen (t>0) + hf/cf copy (t==Tn)
__global__ __launch_bounds__(128) void k_gates(int t,
        const float* __restrict__ Whh, const float* __restrict__ bhh,
        const float* __restrict__ Wout, const float* __restrict__ bout,
        const float* __restrict__ Wpg, const float* __restrict__ bpg,
        float* __restrict__ out) {
    __shared__ float sm[12288];
    int bid = blockIdx.x, tid = threadIdx.x;
    int pin = t & 1;

    if (bid < 128) {                         // ---- gate blocks ----
        if (t >= Tn) return;
        for (int i = tid; i < Hn*Bn; i += 128) sm[i] = g_hT[pin][i];
        __syncthreads();
        int b = tid & 15, c = tid >> 4;      // c = gate*2 + jj
        int gate = c >> 1, jj = c & 1;
        int r = gate*Hn + bid*2 + jj;        // Whh row
        float acc = 0.f;
        const float* wr = &Whh[r*Hn];
        #pragma unroll 8
        for (int k = 0; k < Hn; k += 4) {
            float4 w = ld4(&wr[k]);
            acc += w.x*sm[k*16+b] + w.y*sm[(k+1)*16+b]
                 + w.z*sm[(k+2)*16+b] + w.w*sm[(k+3)*16+b];
        }
        acc += g_xw[(t*Bn + b)*G4n + r] + bhh[r];
        sm[4096 + c*16 + b] = acc;
        __syncthreads();
        if (tid < 32) {
            int b2 = tid & 15, jj2 = tid >> 4;
            int j2 = bid*2 + jj2;
            float gi = sm[4096 + (0+jj2)*16 + b2];
            float gf = sm[4096 + (2+jj2)*16 + b2];
            float gg = sm[4096 + (4+jj2)*16 + b2];
            float go = sm[4096 + (6+jj2)*16 + b2];
            float co = g_cT[pin][j2*16 + b2];
            float cn = sigmoidf_(gf)*co + sigmoidf_(gi)*tanh_acc(gg);
            float hn = sigmoidf_(go)*tanh_acc(cn);
            g_cT[pin^1][j2*16 + b2] = cn;
            g_hT[pin^1][j2*16 + b2] = hn;
        }
    } else if (bid < 160) {                  // ---- out[t-1] blocks ----
        if (t == 0) return;
        for (int i = tid; i < 12288; i += 128)
            sm[i] = (i < 4096) ? g_hT[pin][i] : g_ctxT[i - 4096];
        __syncthreads();
        int b = tid & 15, c = tid >> 4;
        int h = (bid - 128)*8 + c;
        float acc = 0.f;
        const float* wr = &Wout[h*768];
        #pragma unroll 8
        for (int k = 0; k < 768; k += 4) {
            float4 w = ld4(&wr[k]);
            acc += w.x*sm[k*16+b] + w.y*sm[(k+1)*16+b]
                 + w.z*sm[(k+2)*16+b] + w.w*sm[(k+3)*16+b];
        }
        out[OFF_OUT + ((t-1)*Bn + b)*Hn + h] = acc + bout[h];
    } else {                                 // ---- pgen / final state ----
        if (t > 0) {
            int b = tid >> 3, kc = tid & 7;
            float acc = 0.f;
            for (int k = kc*144; k < kc*144 + 144; k++) {
                float val;
                if (k < 512)       val = g_ctxT[k*16 + b];
                else if (k < 768)  val = g_hT[pin][(k-512)*16 + b];
                else if (k < 1024) val = g_cT[pin][(k-768)*16 + b];
                else               val = g_x[((t-1)*Bn + b)*En + (k-1024)];
                acc += val * Wpg[k];
            }
            sm[b*9 + kc] = acc;
        }
        __syncthreads();
        if (t > 0 && tid < 16) {
            float s = 0.f;
            #pragma unroll
            for (int kc = 0; kc < 8; kc++) s += sm[tid*9 + kc];
            out[OFF_PG + (t-1)*Bn + tid] = sigmoidf_(s + bpg[0]);
        }
        if (t == Tn) {
            for (int i = tid; i < Hn*Bn; i += 128) {
                int b2 = i & 15, k = i >> 4;
                out[OFF_HF + b2*Hn + k] = g_hT[pin][i];
                out[OFF_CF + b2*Hn + k] = g_cT[pin][i];
            }
        }
    }
}

// ---------------- k_dec: dec_feat = [h_new;c_new] @ Ws.T + bs ----------------
// grid = 32 blocks x 128 threads (8 cols x 16 b each)
__global__ __launch_bounds__(128) void k_dec(int t,
        const float* __restrict__ Ws, const float* __restrict__ bs) {
    __shared__ float sm[8192];
    int tid = threadIdx.x;
    int pout = (t & 1) ^ 1;
    for (int i = tid; i < 8192; i += 128)
        sm[i] = (i < 4096) ? g_hT[pout][i] : g_cT[pout][i - 4096];
    __syncthreads();
    int b = tid & 15, c = tid >> 4;
    int col = blockIdx.x*8 + c;
    float acc = 0.f;
    const float* wr = &Ws[col*H2n];
    #pragma unroll 8
    for (int k = 0; k < H2n; k += 4) {
        float4 w = ld4(&wr[k]);
        acc += w.x*sm[k*16+b] + w.y*sm[(k+1)*16+b]
             + w.z*sm[(k+2)*16+b] + w.w*sm[(k+3)*16+b];
    }
    g_dec[b*Hn + col] = acc + bs[col];
}

// ---------------- k_scores: logits + softmax partials ----------------
// grid = Bn*NSC = 1024 blocks x 256 threads; block = (b, 32 l's)
__global__ __launch_bounds__(256) void k_scores(int t,
        const float* __restrict__ v, const float* __restrict__ mask) {
    __shared__ float sD[Hn], sV[Hn], sp[32*9];
    int b = blockIdx.x >> 6, lc = blockIdx.x & 63;
    int l0 = lc * 32;
    int tid = threadIdx.x;
    sD[tid] = g_dec[b*Hn + tid];
    sV[tid] = v[tid];
    __syncthreads();
    int kc = tid >> 5, l = tid & 31;          // warp = 32 l at one kc (broadcast smem)
    const float* ef = &g_ef[(size_t)(b*Ln + l0 + l)*Hn + kc*32];
    float acc = 0.f;
    #pragma unroll
    for (int i = 0; i < 4; i++) {
        float4 e1 = ld4(&ef[i*8]);
        float4 e2 = ld4(&ef[i*8 + 4]);
        int k = kc*32 + i*8;
        acc += sV[k  ]*tanh_fast(e1.x + sD[k  ]);
        acc += sV[k+1]*tanh_fast(e1.y + sD[k+1]);
        acc += sV[k+2]*tanh_fast(e1.z + sD[k+2]);
        acc += sV[k+3]*tanh_fast(e1.w + sD[k+3]);
        acc += sV[k+4]*tanh_fast(e2.x + sD[k+4]);
        acc += sV[k+5]*tanh_fast(e2.y + sD[k+5]);
        acc += sV[k+6]*tanh_fast(e2.z + sD[k+6]);
        acc += sV[k+7]*tanh_fast(e2.w + sD[k+7]);
    }
    sp[l*9 + kc] = acc;
    __syncthreads();
    if (tid < 32) {
        float s = 0.f;
        #pragma unroll
        for (int q = 0; q < 8; q++) s += sp[tid*9 + q];
        g_e[b*Ln + l0 + tid] = s;
        float m = warp_max(s);
        float ex = __expf(s - m) * mask[b*Ln + l0 + tid];
        float sx = warp_sum(ex);
        if (tid == 0) { g_m[b*NSC + lc] = m; g_s[b*NSC + lc] = sx; }
    }
}

// ---------------- k_ctx: attn + ctx partials + last-block reduction ----------------
// grid = Bn*NCC = 512 blocks x 256 threads; block = (b, 64 l's)
__global__ __launch_bounds__(256) void k_ctx(int t,
        const float* __restrict__ es, const float* __restrict__ mask,
        float* __restrict__ out) {
    __shared__ float sA[64];
    __shared__ float sred[H2n];
    __shared__ int sticket;
    int b = blockIdx.x >> 5, ch = blockIdx.x & 31;
    int l0 = ch * 64;
    int tid = threadIdx.x;

    float M = -1e30f;
    #pragma unroll 8
    for (int c = 0; c < NSC; c++) M = fmaxf(M, g_m[b*NSC + c]);
    float S = 0.f;
    #pragma unroll 8
    for (int c = 0; c < NSC; c++) S += g_s[b*NSC + c] * __expf(g_m[b*NSC + c] - M);
    float invS = __fdividef(1.f, S);
    if (tid < 64) {
        int l = l0 + tid;
        float a = __expf(g_e[b*Ln + l] - M) * mask[b*Ln + l] * invS;
        out[OFF_ATTN + (size_t)(t*Bn + b)*Ln + l] = a;
        sA[tid] = a;
    }
    __syncthreads();

    int lh = tid >> 7, q = tid & 127;          // e-slot q*4, l-half lh
    float4 acc = make_float4(0.f, 0.f, 0.f, 0.f);
    #pragma unroll 8
    for (int l = lh*32; l < lh*32 + 32; l++) {
        float a = sA[l];
        float4 r = ld4(&es[(size_t)(b*Ln + l0 + l)*H2n + q*4]);
        acc.x += a*r.x; acc.y += a*r.y; acc.z += a*r.z; acc.w += a*r.w;
    }
    if (lh == 1) {
        sred[q*4+0] = acc.x; sred[q*4+1] = acc.y;
        sred[q*4+2] = acc.z; sred[q*4+3] = acc.w;
    }
    __syncthreads();
    if (lh == 0) {
        float* dst = &g_ctxp[(size_t)(b*NCC + ch)*H2n + q*4];
        dst[0] = acc.x + sred[q*4+0];
        dst[1] = acc.y + sred[q*4+1];
        dst[2] = acc.z + sred[q*4+2];
        dst[3] = acc.w + sred[q*4+3];
    }
    // last block for this b reduces partials into g_ctxT (deterministic fixed-order sum)
    __threadfence();
    if (tid == 0) sticket = atomicAdd(&g_cnt[b], 1);
    __syncthreads();
    if (sticket == NCC - 1) {
        __threadfence();
        for (int e = tid; e < H2n; e += 256) {
            float s = 0.f;
            #pragma unroll 8
            for (int p = 0; p < NCC; p++) s += g_ctxp[(size_t)(b*NCC + p)*H2n + e];
            g_ctxT[e*16 + b] = s;
        }
        __threadfence();
        if (tid == 0) g_cnt[b] = 0;
    }
}

// ---------------- launcher ----------------
extern "C" void kernel_launch(void* const* d_in, const int* in_sizes, int n_in,
                              void* d_out, int out_size) {
    const float* dec  = (const float*)d_in[0];
    const float* h0   = (const float*)d_in[1];
    const float* c0   = (const float*)d_in[2];
    const float* es   = (const float*)d_in[3];
    const float* mask = (const float*)d_in[4];
    const float* Wh   = (const float*)d_in[5];
    const float* bh   = (const float*)d_in[6];
    const float* Ws   = (const float*)d_in[7];
    const float* bs   = (const float*)d_in[8];
    const float* v    = (const float*)d_in[9];
    const float* Wx   = (const float*)d_in[10];
    const float* bx   = (const float*)d_in[11];
    const float* Wih  = (const float*)d_in[12];
    const float* bih  = (const float*)d_in[13];
    const float* Whh  = (const float*)d_in[14];
    const float* bhh  = (const float*)d_in[15];
    const float* Wpg  = (const float*)d_in[16];
    const float* bpg  = (const float*)d_in[17];
    const float* Wout = (const float*)d_in[18];
    const float* bout = (const float*)d_in[19];
    float* out = (float*)d_out;

    k_prep<<<16, 256>>>(h0, c0);
    k_xfuse<<<200, 256>>>(dec, Wx, bx, Wih, bih);
    k_encfeat<<<1024, 256>>>(es, Wh, bh);
    for (int t = 0; t < Tn; t++) {
        k_gates<<<161, 128>>>(t, Whh, bhh, Wout, bout, Wpg, bpg, out);
        k_dec<<<32, 128>>>(t, Ws, bs);
        k_scores<<<Bn*NSC, 256>>>(t, v, mask);
        k_ctx<<<Bn*NCC, 256>>>(t, es, mask, out);
    }
    k_gates<<<161, 128>>>(Tn, Whh, bhh, Wout, bout, Wpg, bpg, out);
}

// round 6
// speedup vs baseline: 1.5978x; 1.0933x over previous
#include <cuda_runtime.h>
#include <cuda_bf16.h>

#define Tn 100
#define Bn 16
#define En 128
#define Hn 256
#define Ln 2048
#define H2n 512
#define G4n 1024
#define NSC 64      // score chunks (32 l each)
#define NCC 32      // ctx chunks (64 l each)
#define NB 148
#define NT 256

#define OFF_OUT  0
#define OFF_HF   (Tn*Bn*Hn)
#define OFF_CF   (OFF_HF + Bn*Hn)
#define OFF_ATTN (OFF_CF + Bn*Hn)
#define OFF_PG   (OFF_ATTN + Tn*Bn*Ln)

// ---------------- scratch ----------------
__device__ float g_x[Tn*Bn*En];
__device__ float g_xw[Tn*Bn*G4n];
__device__ float g_ef[Bn*Ln*Hn];
__device__ float g_e[Bn*Ln];
__device__ float g_m[Bn*NSC];
__device__ float g_s[Bn*NSC];
__device__ float g_hT[2][Hn*Bn];      // [k][b]
__device__ float g_cT[2][Hn*Bn];
__device__ float g_ctxT[H2n*Bn];      // [e][b]
__device__ float g_dec[Bn*Hn];        // [b][k]
__device__ float g_ctxp[Bn*NCC*H2n]; // [b][chunk][e]
__device__ unsigned g_bar;

// ---------------- helpers ----------------
__device__ __forceinline__ float warp_sum(float v) {
    #pragma unroll
    for (int o = 16; o > 0; o >>= 1) v += __shfl_xor_sync(0xffffffffu, v, o);
    return v;
}
__device__ __forceinline__ float warp_max(float v) {
    #pragma unroll
    for (int o = 16; o > 0; o >>= 1) v = fmaxf(v, __shfl_xor_sync(0xffffffffu, v, o));
    return v;
}
__device__ __forceinline__ float tanh_acc(float x) {   // accurate (LSTM recurrence)
    float ax = fabsf(x);
    float e  = __expf(-2.0f * ax);
    float r  = __fdividef(1.0f - e, 1.0f + e);
    return copysignf(r, x);
}
__device__ __forceinline__ float tanh_fast(float x) {  // MUFU.TANH (attention)
    float y;
    asm("tanh.approx.f32 %0, %1;" : "=f"(y) : "f"(x));
    return y;
}
__device__ __forceinline__ float sigmoidf_(float x) {
    return __fdividef(1.0f, 1.0f + __expf(-x));
}
__device__ __forceinline__ float4 ld4(const float* p) { return *(const float4*)p; }

__device__ __forceinline__ void grid_bar(unsigned& ep) {
    __syncthreads();
    ep += NB;
    if (threadIdx.x == 0) {
        __threadfence();
        atomicAdd(&g_bar, 1u);
        unsigned cur;
        do {
            asm volatile("ld.acquire.gpu.u32 %0, [%1];" : "=r"(cur) : "l"(&g_bar));
            if (cur < ep) __nanosleep(32);
        } while (cur < ep);
    }
    __syncthreads();
}

// ---------------- zero barrier counter ----------------
__global__ void k_zero() { g_bar = 0u; }

// ---------------- prep: transpose h0/c0 ----------------
__global__ void k_prep(const float* __restrict__ h0, const float* __restrict__ c0) {
    int i = blockIdx.x * blockDim.x + threadIdx.x;
    if (i < Hn*Bn) {
        int b = i & 15, k = i >> 4;
        g_hT[0][i] = h0[b*Hn + k];
        g_cT[0][i] = c0[b*Hn + k];
    }
}

// ---------------- x and x@Wih.T for all (t,b) ----------------
__global__ __launch_bounds__(256) void k_xfuse(const float* __restrict__ dec,
        const float* __restrict__ Wx, const float* __restrict__ bx,
        const float* __restrict__ Wih, const float* __restrict__ bih) {
    __shared__ float sin_[8][En];
    __shared__ float sx2[8][En];
    int r0 = blockIdx.x * 8;
    int tid = threadIdx.x;
    for (int idx = tid; idx < 8*En; idx += 256)
        sin_[idx >> 7][idx & 127] = dec[(r0 + (idx >> 7))*En + (idx & 127)];
    __syncthreads();
    {
        int j = tid & 127, rg = tid >> 7;
        float acc[4] = {0.f, 0.f, 0.f, 0.f};
        #pragma unroll 8
        for (int k = 0; k < En; k += 4) {
            float4 w = ld4(&Wx[j*640 + k]);
            #pragma unroll
            for (int rr = 0; rr < 4; rr++) {
                const float* s = sin_[rg*4 + rr];
                acc[rr] += w.x*s[k] + w.y*s[k+1] + w.z*s[k+2] + w.w*s[k+3];
            }
        }
        float bb = bx[j];
        #pragma unroll
        for (int rr = 0; rr < 4; rr++) {
            float val = acc[rr] + bb;
            sx2[rg*4 + rr][j] = val;
            g_x[(r0 + rg*4 + rr)*En + j] = val;
        }
    }
    __syncthreads();
    for (int q = 0; q < 4; q++) {
        int g = q*256 + tid;
        float acc[8];
        #pragma unroll
        for (int r = 0; r < 8; r++) acc[r] = 0.f;
        #pragma unroll 4
        for (int k = 0; k < En; k += 4) {
            float4 w = ld4(&Wih[g*En + k]);
            #pragma unroll
            for (int r = 0; r < 8; r++)
                acc[r] += w.x*sx2[r][k] + w.y*sx2[r][k+1] + w.z*sx2[r][k+2] + w.w*sx2[r][k+3];
        }
        float bb = bih[g];
        #pragma unroll
        for (int r = 0; r < 8; r++) g_xw[(r0 + r)*G4n + g] = acc[r] + bb;
    }
}

// ---------------- enc_feat = es @ Wh.T + bh ----------------
__global__ __launch_bounds__(256) void k_encfeat(const float* __restrict__ es,
        const float* __restrict__ Wh, const float* __restrict__ bh) {
    __shared__ float sW[32*261];
    __shared__ float sE[32*36];
    int b  = blockIdx.x >> 6;
    int l0 = (blockIdx.x & 63) * 32;
    int tid = threadIdx.x, lane = tid & 31, w = tid >> 5;
    float acc[32];
    #pragma unroll
    for (int i = 0; i < 32; i++) acc[i] = 0.f;
    for (int k0 = 0; k0 < H2n; k0 += 32) {
        #pragma unroll 4
        for (int hh = 0; hh < 32; hh++) {
            int h = w*32 + hh;
            sW[lane*261 + h] = Wh[h*H2n + k0 + lane];
        }
        for (int idx = tid; idx < 1024; idx += 256) {
            int l = idx >> 5, k = idx & 31;
            sE[k*36 + l] = es[(size_t)(b*Ln + l0 + l)*H2n + k0 + k];
        }
        __syncthreads();
        #pragma unroll 4
        for (int k = 0; k < 32; k++) {
            float wv = sW[k*261 + tid];
            #pragma unroll
            for (int i4 = 0; i4 < 8; i4++) {
                float4 e = ld4(&sE[k*36 + i4*4]);
                acc[i4*4+0] += e.x*wv; acc[i4*4+1] += e.y*wv;
                acc[i4*4+2] += e.z*wv; acc[i4*4+3] += e.w*wv;
            }
        }
        __syncthreads();
    }
    float bb = bh[tid];
    #pragma unroll
    for (int i = 0; i < 32; i++)
        g_ef[(size_t)(b*Ln + l0 + i)*Hn + tid] = acc[i] + bb;
}

// ---------------- persistent step loop ----------------
__global__ __launch_bounds__(NT, 2) void k_persist(
        const float* __restrict__ Whh, const float* __restrict__ bhh,
        const float* __restrict__ Wout, const float* __restrict__ bout,
        const float* __restrict__ Wpg, const float* __restrict__ bpg,
        const float* __restrict__ Ws, const float* __restrict__ bs,
        const float* __restrict__ v, const float* __restrict__ mask,
        const float* __restrict__ es, float* __restrict__ out) {
    __shared__ float sm[1088];
    int bid = blockIdx.x, tid = threadIdx.x;
    unsigned ep = 0;

    for (int t = 0; t <= Tn; t++) {
        int pin = t & 1;

        // ======== P1: gates(t) + reduce ctx(t-1) ========
        if (t < Tn && bid < 64) {
            int b = tid & 15, c = tid >> 4;
            int gate = c >> 2, jj = c & 3;
            int r = gate*Hn + bid*4 + jj;
            const float* wr = &Whh[r*Hn];
            const float* hp = g_hT[pin];
            float acc = 0.f;
            #pragma unroll 8
            for (int k = 0; k < Hn; k += 4) {
                float4 w = ld4(&wr[k]);
                acc += w.x*hp[k*16+b]     + w.y*hp[(k+1)*16+b]
                     + w.z*hp[(k+2)*16+b] + w.w*hp[(k+3)*16+b];
            }
            acc += g_xw[(t*Bn + b)*G4n + r] + bhh[r];
            sm[c*16 + b] = acc;
            __syncthreads();
            if (tid < 64) {
                int b2 = tid & 15, jj2 = tid >> 4;
                int j2 = bid*4 + jj2;
                float gi = sm[(0*4+jj2)*16 + b2];
                float gf = sm[(1*4+jj2)*16 + b2];
                float gg = sm[(2*4+jj2)*16 + b2];
                float go = sm[(3*4+jj2)*16 + b2];
                float co = g_cT[pin][j2*16 + b2];
                float cn = sigmoidf_(gf)*co + sigmoidf_(gi)*tanh_acc(gg);
                float hn = sigmoidf_(go)*tanh_acc(cn);
                g_cT[pin^1][j2*16 + b2] = cn;
                g_hT[pin^1][j2*16 + b2] = hn;
            }
        } else if (t > 0 && bid >= 64 && bid < 80) {
            int b = bid - 64;
            for (int e = tid; e < H2n; e += NT) {
                float s = 0.f;
                #pragma unroll 8
                for (int p = 0; p < NCC; p++) s += g_ctxp[(b*NCC + p)*H2n + e];
                g_ctxT[e*16 + b] = s;
            }
        }
        grid_bar(ep);

        // ======== P2: out/pgen epilogue (t>0), dec_feat (t<Tn), final state (t==Tn) ========
        if (t > 0 && bid < 16) {
            int b = tid & 15, c = tid >> 4;
            int h = bid*16 + c;
            const float* wr = &Wout[h*768];
            const float* hp = g_hT[pin];
            float acc = 0.f;
            #pragma unroll 8
            for (int k = 0; k < 768; k += 4) {
                float4 w = ld4(&wr[k]);
                const float* src = (k < 256) ? &hp[k*16 + b] : &g_ctxT[(k-256)*16 + b];
                acc += w.x*src[0] + w.y*src[16] + w.z*src[32] + w.w*src[48];
            }
            out[OFF_OUT + ((t-1)*Bn + b)*Hn + h] = acc + bout[h];
        } else if (t < Tn && bid >= 16 && bid < 32) {
            int b = tid & 15, c = tid >> 4;
            int col = (bid - 16)*16 + c;
            const float* wr = &Ws[col*H2n];
            const float* hp = g_hT[pin^1];
            const float* cp = g_cT[pin^1];
            float acc = 0.f;
            #pragma unroll 8
            for (int k = 0; k < H2n; k += 4) {
                float4 w = ld4(&wr[k]);
                const float* src = (k < 256) ? &hp[k*16 + b] : &cp[(k-256)*16 + b];
                acc += w.x*src[0] + w.y*src[16] + w.z*src[32] + w.w*src[48];
            }
            g_dec[b*Hn + col] = acc + bs[col];
        } else if (t > 0 && bid == 32) {
            int b = tid >> 4, kc = tid & 15;
            const float* hp = g_hT[pin];
            const float* cp = g_cT[pin];
            float acc = 0.f;
            for (int k = kc*72; k < kc*72 + 72; k++) {
                float val;
                if (k < 512)       val = g_ctxT[k*16 + b];
                else if (k < 768)  val = hp[(k-512)*16 + b];
                else if (k < 1024) val = cp[(k-768)*16 + b];
                else               val = g_x[((t-1)*Bn + b)*En + (k-1024)];
                acc += val * Wpg[k];
            }
            sm[tid] = acc;
            __syncthreads();
            if (tid < 16) {
                float s = 0.f;
                #pragma unroll
                for (int q = 0; q < 16; q++) s += sm[tid*16 + q];
                out[OFF_PG + (t-1)*Bn + tid] = sigmoidf_(s + bpg[0]);
            }
        } else if (t == Tn && bid == 33) {
            for (int i = tid; i < Hn*Bn; i += NT) {
                int b = i & 15, k = i >> 4;
                out[OFF_HF + b*Hn + k] = g_hT[pin][i];
                out[OFF_CF + b*Hn + k] = g_cT[pin][i];
            }
        }
        grid_bar(ep);

        if (t == Tn) break;

        // ======== C: scores + softmax partials ========
        {
            float* sD = sm; float* sV = sm + 256; float* sp = sm + 512;
            for (int wi = bid; wi < Bn*NSC; wi += NB) {
                int b = wi >> 6, lc = wi & 63, l0 = lc*32;
                sD[tid] = g_dec[b*Hn + tid];
                sV[tid] = v[tid];
                __syncthreads();
                int kc = tid >> 5, l = tid & 31;
                const float* ef = &g_ef[(size_t)(b*Ln + l0 + l)*Hn + kc*32];
                float acc = 0.f;
                #pragma unroll
                for (int i = 0; i < 4; i++) {
                    float4 e1 = ld4(&ef[i*8]);
                    float4 e2 = ld4(&ef[i*8 + 4]);
                    int k = kc*32 + i*8;
                    acc += sV[k  ]*tanh_fast(e1.x + sD[k  ]);
                    acc += sV[k+1]*tanh_fast(e1.y + sD[k+1]);
                    acc += sV[k+2]*tanh_fast(e1.z + sD[k+2]);
                    acc += sV[k+3]*tanh_fast(e1.w + sD[k+3]);
                    acc += sV[k+4]*tanh_fast(e2.x + sD[k+4]);
                    acc += sV[k+5]*tanh_fast(e2.y + sD[k+5]);
                    acc += sV[k+6]*tanh_fast(e2.z + sD[k+6]);
                    acc += sV[k+7]*tanh_fast(e2.w + sD[k+7]);
                }
                sp[l*9 + kc] = acc;
                __syncthreads();
                if (tid < 32) {
                    float s = 0.f;
                    #pragma unroll
                    for (int q = 0; q < 8; q++) s += sp[tid*9 + q];
                    g_e[b*Ln + l0 + tid] = s;
                    float m = warp_max(s);
                    float exv = __expf(s - m) * mask[b*Ln + l0 + tid];
                    float sx = warp_sum(exv);
                    if (tid == 0) { g_m[b*NSC + lc] = m; g_s[b*NSC + lc] = sx; }
                }
                __syncthreads();
            }
        }
        grid_bar(ep);

        // ======== D: attn + ctx partials ========
        {
            float* sA = sm; float* sred = sm + 64;
            for (int wi = bid; wi < Bn*NCC; wi += NB) {
                int b = wi >> 5, ch = wi & 31, l0 = ch*64;
                float M = -1e30f;
                #pragma unroll 8
                for (int c = 0; c < NSC; c++) M = fmaxf(M, g_m[b*NSC + c]);
                float S = 0.f;
                #pragma unroll 8
                for (int c = 0; c < NSC; c++) S += g_s[b*NSC + c] * __expf(g_m[b*NSC + c] - M);
                float invS = __fdividef(1.f, S);
                if (tid < 64) {
                    int l = l0 + tid;
                    float a = __expf(g_e[b*Ln + l] - M) * mask[b*Ln + l] * invS;
                    out[OFF_ATTN + (size_t)(t*Bn + b)*Ln + l] = a;
                    sA[tid] = a;
                }
                __syncthreads();
                int lh = tid >> 7, q = tid & 127;
                float4 acc = make_float4(0.f, 0.f, 0.f, 0.f);
                #pragma unroll 8
                for (int l = lh*32; l < lh*32 + 32; l++) {
                    float a = sA[l];
                    float4 r = ld4(&es[(size_t)(b*Ln + l0 + l)*H2n + q*4]);
                    acc.x += a*r.x; acc.y += a*r.y; acc.z += a*r.z; acc.w += a*r.w;
                }
                if (lh == 1) {
                    sred[q*4+0] = acc.x; sred[q*4+1] = acc.y;
                    sred[q*4+2] = acc.z; sred[q*4+3] = acc.w;
                }
                __syncthreads();
                if (lh == 0) {
                    float* dst = &g_ctxp[(size_t)(b*NCC + ch)*H2n + q*4];
                    dst[0] = acc.x + sred[q*4+0];
                    dst[1] = acc.y + sred[q*4+1];
                    dst[2] = acc.z + sred[q*4+2];
                    dst[3] = acc.w + sred[q*4+3];
                }
                __syncthreads();
            }
        }
        grid_bar(ep);
    }
}

// ---------------- launcher ----------------
extern "C" void kernel_launch(void* const* d_in, const int* in_sizes, int n_in,
                              void* d_out, int out_size) {
    const float* dec  = (const float*)d_in[0];
    const float* h0   = (const float*)d_in[1];
    const float* c0   = (const float*)d_in[2];
    const float* es   = (const float*)d_in[3];
    const float* mask = (const float*)d_in[4];
    const float* Wh   = (const float*)d_in[5];
    const float* bh   = (const float*)d_in[6];
    const float* Ws   = (const float*)d_in[7];
    const float* bs   = (const float*)d_in[8];
    const float* v    = (const float*)d_in[9];
    const float* Wx   = (const float*)d_in[10];
    const float* bx   = (const float*)d_in[11];
    const float* Wih  = (const float*)d_in[12];
    const float* bih  = (const float*)d_in[13];
    const float* Whh  = (const float*)d_in[14];
    const float* bhh  = (const float*)d_in[15];
    const float* Wpg  = (const float*)d_in[16];
    const float* bpg  = (const float*)d_in[17];
    const float* Wout = (const float*)d_in[18];
    const float* bout = (const float*)d_in[19];
    float* out = (float*)d_out;

    k_zero<<<1, 1>>>();
    k_prep<<<16, 256>>>(h0, c0);
    k_xfuse<<<200, 256>>>(dec, Wx, bx, Wih, bih);
    k_encfeat<<<1024, 256>>>(es, Wh, bh);
    k_persist<<<NB, NT>>>(Whh, bhh, Wout, bout, Wpg, bpg, Ws, bs, v, mask, es, out);
}